// round 6
// baseline (speedup 1.0000x reference)
#include <cuda_runtime.h>
#include <cuda_bf16.h>
#include <math.h>

// ---------------- problem constants ----------------
#define Bz   64
#define Tt   12
#define Nn   1024
#define Hh   64
#define Mm   32
#define Kk   3
#define HOR  12
#define DIN  65            // C + H = 1 + 64
#define G4   256           // 4*H
#define Pp   195           // K*DIN
#define SCP  196           // padded sc row
#define BT   (Bz*Tt)       // 768
#define WMC  (Pp*G4)       // 49920

// ---------------- device scratch (no allocs allowed) ----------------
__device__ float g_h[(size_t)Bz*Nn*Hh];        // 16 MB
__device__ float g_c[(size_t)Bz*Nn*Hh];        // 16 MB
__device__ float g_sc[(size_t)Bz*Nn*SCP];      // 51 MB
__device__ float g_Wm[(size_t)BT*WMC];         // 153 MB
__device__ float g_bm[(size_t)BT*G4];
__device__ float g_hid1[BT*64];
__device__ float g_hid2[BT*64];
__device__ float g_x[Bz*Nn];                   // decoder input column

// ---------------- init kernels ----------------
__global__ void zero_hc_kernel() {
    size_t i = (size_t)blockIdx.x * blockDim.x + threadIdx.x;
    g_h[i] = 0.f; g_c[i] = 0.f;
}
__global__ void zero_x_kernel() {
    int i = blockIdx.x * blockDim.x + threadIdx.x;
    g_x[i] = 0.f;
}

// ---------------- meta MLPs ----------------
// hidden1 = relu(x_meta @ lw1_w + lw1_b), hidden2 = relu(x_meta @ lb1_w + lb1_b)
__global__ void meta1_kernel(const float* __restrict__ xm,
                             const float* __restrict__ lw1w, const float* __restrict__ lw1b,
                             const float* __restrict__ lb1w, const float* __restrict__ lb1b) {
    int bt = blockIdx.x;
    int o  = threadIdx.x & 63;
    bool second = threadIdx.x >= 64;
    const float* W  = second ? lb1w : lw1w;
    const float* bi = second ? lb1b : lw1b;
    float acc = bi[o];
    const float* x = xm + bt * Mm;
    #pragma unroll
    for (int m = 0; m < Mm; m++) acc += x[m] * W[m * 64 + o];
    acc = fmaxf(acc, 0.f);
    if (second) g_hid2[bt * 64 + o] = acc;
    else        g_hid1[bt * 64 + o] = acc;
}

// Wm = hidden1 @ lw2_w + lw2_b  -> [BT, 49920]
__global__ void meta2_kernel(const float* __restrict__ lw2w, const float* __restrict__ lw2b) {
    int q0 = blockIdx.x * 256;
    int r0 = blockIdx.y * 16;
    __shared__ float hs[16][65];
    int tid = threadIdx.x;
    {
        int r = tid >> 6, c = tid & 63;
        #pragma unroll
        for (int i = 0; i < 4; i++)
            hs[r + i * 4][c] = g_hid1[(r0 + r + i * 4) * 64 + c];
    }
    __syncthreads();
    float acc[16];
    #pragma unroll
    for (int r = 0; r < 16; r++) acc[r] = 0.f;
    int q = q0 + tid;
    #pragma unroll 8
    for (int i = 0; i < 64; i++) {
        float w = lw2w[(size_t)i * WMC + q];
        #pragma unroll
        for (int r = 0; r < 16; r++) acc[r] += hs[r][i] * w;
    }
    float bv = lw2b[q];
    #pragma unroll
    for (int r = 0; r < 16; r++)
        g_Wm[(size_t)(r0 + r) * WMC + q] = acc[r] + bv;
}

// bm = hidden2 @ lb2_w + lb2_b  -> [BT, 256]
__global__ void meta2b_kernel(const float* __restrict__ lb2w, const float* __restrict__ lb2b) {
    int bt = blockIdx.x, q = threadIdx.x;
    float acc = lb2b[q];
    const float* hrow = g_hid2 + bt * 64;
    #pragma unroll
    for (int i = 0; i < 64; i++) acc += hrow[i] * lb2w[i * G4 + q];
    g_bm[bt * G4 + q] = acc;
}

// ---------------- GCN: sc[b,n,k*65+p] = sum_m G[k,n,m]*comb[b,m,p] ----------------
// comb col 0 = x (x_seq slice or g_x), cols 1..64 = h.
// Block: 64 rows(n) x 64 h-cols (+1 x col), 256 threads, 4x4 microtile.
__global__ void gcn_kernel(const float* __restrict__ G,
                           const float* __restrict__ xsrc, int x_bstride, int use_gx) {
    const int n0 = blockIdx.x * 64;
    const int k  = blockIdx.y;
    const int b  = blockIdx.z;
    __shared__ __align__(16) float Gs[32][68];   // [m_local][n_local]
    __shared__ __align__(16) float Cs[32][68];   // [m_local][col]: 0..63 = h, 64 = x
    const int tid = threadIdx.x;
    const int tx = tid & 15, ty = tid >> 4;
    const float* xs = use_gx ? g_x : xsrc;
    const int xbs   = use_gx ? Nn : x_bstride;

    float acc[4][4];
    #pragma unroll
    for (int i = 0; i < 4; i++)
        #pragma unroll
        for (int j = 0; j < 4; j++) acc[i][j] = 0.f;
    float accx[4] = {0.f, 0.f, 0.f, 0.f};

    const float* Gbase = G + (size_t)k * Nn * Nn;
    for (int m0 = 0; m0 < Nn; m0 += 32) {
        // G tile: 64 rows x 32 m (stored transposed: Gs[m][n_local])
        {
            int r = tid >> 5, c = tid & 31;
            #pragma unroll
            for (int i = 0; i < 8; i++)
                Gs[c][r + i * 8] = Gbase[(size_t)(n0 + r + i * 8) * Nn + m0 + c];
        }
        // comb tile: 32 m x (64 h + 1 x)
        {
            int rr = tid >> 6, j = tid & 63;
            #pragma unroll
            for (int i = 0; i < 8; i++) {
                int r = rr + i * 4;
                Cs[r][j] = g_h[((size_t)b * Nn + m0 + r) * Hh + j];
            }
            if (tid < 32) Cs[tid][64] = xs[(size_t)b * xbs + m0 + tid];
        }
        __syncthreads();
        #pragma unroll
        for (int kk = 0; kk < 32; kk++) {
            float4 gv = *reinterpret_cast<const float4*>(&Gs[kk][ty * 4]);
            float4 cv = *reinterpret_cast<const float4*>(&Cs[kk][tx * 4]);
            float gvv[4] = {gv.x, gv.y, gv.z, gv.w};
            float cvv[4] = {cv.x, cv.y, cv.z, cv.w};
            #pragma unroll
            for (int i = 0; i < 4; i++)
                #pragma unroll
                for (int j = 0; j < 4; j++)
                    acc[i][j] += gvv[i] * cvv[j];
            if (tx == 0) {
                float xv = Cs[kk][64];
                #pragma unroll
                for (int i = 0; i < 4; i++) accx[i] += gvv[i] * xv;
            }
        }
        __syncthreads();
    }
    #pragma unroll
    for (int i = 0; i < 4; i++) {
        int n = n0 + ty * 4 + i;
        float* dst = g_sc + ((size_t)b * Nn + n) * SCP + k * DIN;
        #pragma unroll
        for (int j = 0; j < 4; j++) dst[1 + tx * 4 + j] = acc[i][j];
        if (tx == 0) dst[0] = accx[i];
    }
}

// ---------------- conv + LSTM: conv = sc @ W + bias; (h,c) update ----------------
// Block: 32 rows x 256 gate-cols, 256 threads, each owns 8 rows x 4 gates for one h.
__global__ void convlstm_kernel(int t, int per_batch,
                                const float* __restrict__ Wext,
                                const float* __restrict__ bext) {
    const int n0 = blockIdx.x * 32;
    const int b  = blockIdx.y;
    const int tid = threadIdx.x;
    const int hq = tid & 63;
    const int rg = tid >> 6;
    __shared__ float scs[32][17];
    __shared__ float wms[16][260];
    const float* Wb = per_batch ? (g_Wm + (size_t)(b * Tt + t) * WMC) : Wext;
    const float* bb = per_batch ? (g_bm + (size_t)(b * Tt + t) * G4) : bext;

    float acc[8][4];
    #pragma unroll
    for (int j = 0; j < 8; j++)
        #pragma unroll
        for (int g = 0; g < 4; g++) acc[j][g] = 0.f;

    for (int p0 = 0; p0 < Pp; p0 += 16) {
        {   // sc tile 32 x 16
            int r = tid >> 3, c = tid & 7;
            #pragma unroll
            for (int i = 0; i < 2; i++) {
                int p = p0 + c + i * 8;
                scs[r][c + i * 8] = (p < Pp) ? g_sc[((size_t)b * Nn + n0 + r) * SCP + p] : 0.f;
            }
        }
        {   // W tile 16 x 256
            #pragma unroll
            for (int pp = 0; pp < 16; pp++) {
                int p = p0 + pp;
                wms[pp][tid] = (p < Pp) ? Wb[(size_t)p * G4 + tid] : 0.f;
            }
        }
        __syncthreads();
        #pragma unroll
        for (int pp = 0; pp < 16; pp++) {
            float wv[4];
            #pragma unroll
            for (int g = 0; g < 4; g++) wv[g] = wms[pp][g * 64 + hq];
            #pragma unroll
            for (int j = 0; j < 8; j++) {
                float sv = scs[j * 4 + rg][pp];
                #pragma unroll
                for (int g = 0; g < 4; g++) acc[j][g] += sv * wv[g];
            }
        }
        __syncthreads();
    }
    float bi = bb[hq], bf = bb[64 + hq], bo = bb[128 + hq], bg = bb[192 + hq];
    #pragma unroll
    for (int j = 0; j < 8; j++) {
        int n = n0 + j * 4 + rg;
        float gi = acc[j][0] + bi;
        float gf = acc[j][1] + bf;
        float go = acc[j][2] + bo;
        float gg = acc[j][3] + bg;
        float iv = 1.f / (1.f + expf(-gi));
        float fv = 1.f / (1.f + expf(-gf));
        float ov = 1.f / (1.f + expf(-go));
        float gv = tanhf(gg);
        size_t idx = ((size_t)b * Nn + n) * Hh + hq;
        float cv = fv * g_c[idx] + iv * gv;
        g_c[idx] = cv;
        g_h[idx] = ov * tanhf(cv);
    }
}

// ---------------- decoder projection: out = h @ proj_w + proj_b ----------------
__global__ void proj_kernel(const float* __restrict__ proj_w,
                            const float* __restrict__ proj_b,
                            float* __restrict__ out, int s) {
    int row  = blockIdx.x * 8 + (threadIdx.x >> 5);   // [0, B*N)
    int lane = threadIdx.x & 31;
    const float* hrow = g_h + (size_t)row * Hh;
    float v = hrow[lane] * proj_w[lane] + hrow[lane + 32] * proj_w[lane + 32];
    #pragma unroll
    for (int o = 16; o; o >>= 1) v += __shfl_down_sync(0xffffffffu, v, o);
    if (lane == 0) {
        float r = v + proj_b[0];
        int b = row >> 10, n = row & 1023;
        out[((size_t)b * HOR + s) * Nn + n] = r;
        g_x[row] = r;
    }
}

// ---------------- launch ----------------
extern "C" void kernel_launch(void* const* d_in, const int* in_sizes, int n_in,
                              void* d_out, int out_size) {
    const float* G      = (const float*)d_in[0];
    const float* x_seq  = (const float*)d_in[1];
    const float* x_meta = (const float*)d_in[2];
    const float* lw1_w  = (const float*)d_in[3];
    const float* lw1_b  = (const float*)d_in[4];
    const float* lw2_w  = (const float*)d_in[5];
    const float* lw2_b  = (const float*)d_in[6];
    const float* lb1_w  = (const float*)d_in[7];
    const float* lb1_b  = (const float*)d_in[8];
    const float* lb2_w  = (const float*)d_in[9];
    const float* lb2_b  = (const float*)d_in[10];
    const float* dec_W  = (const float*)d_in[11];
    const float* dec_b  = (const float*)d_in[12];
    const float* proj_w = (const float*)d_in[13];
    const float* proj_b = (const float*)d_in[14];
    float* out = (float*)d_out;

    zero_hc_kernel<<<(Bz * Nn * Hh) / 256, 256>>>();
    meta1_kernel<<<BT, 128>>>(x_meta, lw1_w, lw1_b, lb1_w, lb1_b);
    meta2_kernel<<<dim3(WMC / 256, BT / 16), 256>>>(lw2_w, lw2_b);
    meta2b_kernel<<<BT, 256>>>(lb2_w, lb2_b);

    // encoder
    for (int t = 0; t < Tt; t++) {
        gcn_kernel<<<dim3(Nn / 64, Kk, Bz), 256>>>(G, x_seq + (size_t)t * Nn, Tt * Nn, 0);
        convlstm_kernel<<<dim3(Nn / 32, Bz), 256>>>(t, 1, nullptr, nullptr);
    }

    // decoder
    zero_x_kernel<<<(Bz * Nn) / 256, 256>>>();
    for (int s = 0; s < HOR; s++) {
        gcn_kernel<<<dim3(Nn / 64, Kk, Bz), 256>>>(G, nullptr, Nn, 1);
        convlstm_kernel<<<dim3(Nn / 32, Bz), 256>>>(0, 0, dec_W, dec_b);
        proj_kernel<<<(Bz * Nn) / 8, 256>>>(proj_w, proj_b, out, s);
    }
}

// round 7
// speedup vs baseline: 1.0553x; 1.0553x over previous
#include <cuda_runtime.h>
#include <cuda_bf16.h>
#include <math.h>

// ---------------- problem constants ----------------
#define Bz   64
#define Tt   12
#define Nn   1024
#define Hh   64
#define Mm   32
#define Kk   3
#define HOR  12
#define DIN  65            // C + H = 1 + 64
#define G4   256           // 4*H
#define Pp   195           // K*DIN
#define SCP  196           // padded sc row
#define BT   (Bz*Tt)       // 768
#define WMC  (Pp*G4)       // 49920

// ---------------- device scratch (no allocs allowed) ----------------
__device__ float g_h[(size_t)Bz*Nn*Hh];        // 16 MB
__device__ float g_c[(size_t)Bz*Nn*Hh];        // 16 MB
__device__ float g_sc[(size_t)Bz*Nn*SCP];      // 51 MB
__device__ float g_Wm[(size_t)BT*WMC];         // 153 MB
__device__ float g_bm[(size_t)BT*G4];
__device__ float g_hid1[BT*64];
__device__ float g_hid2[BT*64];
__device__ float g_x[Bz*Nn];                   // decoder input column

// ---------------- init kernels ----------------
__global__ void zero_hc_kernel() {
    size_t i = (size_t)blockIdx.x * blockDim.x + threadIdx.x;
    g_h[i] = 0.f; g_c[i] = 0.f;
}
__global__ void zero_x_kernel() {
    int i = blockIdx.x * blockDim.x + threadIdx.x;
    g_x[i] = 0.f;
}

// ---------------- meta MLPs ----------------
// hidden1 = relu(x_meta @ lw1_w + lw1_b), hidden2 = relu(x_meta @ lb1_w + lb1_b)
__global__ void meta1_kernel(const float* __restrict__ xm,
                             const float* __restrict__ lw1w, const float* __restrict__ lw1b,
                             const float* __restrict__ lb1w, const float* __restrict__ lb1b) {
    int bt = blockIdx.x;
    int o  = threadIdx.x & 63;
    bool second = threadIdx.x >= 64;
    const float* W  = second ? lb1w : lw1w;
    const float* bi = second ? lb1b : lw1b;
    float acc = bi[o];
    const float* x = xm + bt * Mm;
    #pragma unroll
    for (int m = 0; m < Mm; m++) acc += x[m] * W[m * 64 + o];
    acc = fmaxf(acc, 0.f);
    if (second) g_hid2[bt * 64 + o] = acc;
    else        g_hid1[bt * 64 + o] = acc;
}

// Wm = hidden1 @ lw2_w + lw2_b  -> [BT, 49920]
__global__ void meta2_kernel(const float* __restrict__ lw2w, const float* __restrict__ lw2b) {
    int q0 = blockIdx.x * 256;
    int r0 = blockIdx.y * 16;
    __shared__ float hs[16][65];
    int tid = threadIdx.x;
    {
        int r = tid >> 6, c = tid & 63;
        #pragma unroll
        for (int i = 0; i < 4; i++)
            hs[r + i * 4][c] = g_hid1[(r0 + r + i * 4) * 64 + c];
    }
    __syncthreads();
    float acc[16];
    #pragma unroll
    for (int r = 0; r < 16; r++) acc[r] = 0.f;
    int q = q0 + tid;
    #pragma unroll 8
    for (int i = 0; i < 64; i++) {
        float w = lw2w[(size_t)i * WMC + q];
        #pragma unroll
        for (int r = 0; r < 16; r++) acc[r] += hs[r][i] * w;
    }
    float bv = lw2b[q];
    #pragma unroll
    for (int r = 0; r < 16; r++)
        g_Wm[(size_t)(r0 + r) * WMC + q] = acc[r] + bv;
}

// bm = hidden2 @ lb2_w + lb2_b  -> [BT, 256]
__global__ void meta2b_kernel(const float* __restrict__ lb2w, const float* __restrict__ lb2b) {
    int bt = blockIdx.x, q = threadIdx.x;
    float acc = lb2b[q];
    const float* hrow = g_hid2 + bt * 64;
    #pragma unroll
    for (int i = 0; i < 64; i++) acc += hrow[i] * lb2w[i * G4 + q];
    g_bm[bt * G4 + q] = acc;
}

// ---------------- GCN: sc[b,n,k*65+p] = sum_m G[k,n,m]*comb[b,m,p] ----------------
// comb col 0 = x (x_seq slice or g_x), cols 1..64 = h.
// Block: 64 rows(n) x 64 h-cols (+1 x col), 256 threads, 4x4 microtile.
__global__ void gcn_kernel(const float* __restrict__ G,
                           const float* __restrict__ xsrc, int x_bstride, int use_gx) {
    const int n0 = blockIdx.x * 64;
    const int k  = blockIdx.y;
    const int b  = blockIdx.z;
    __shared__ __align__(16) float Gs[32][68];   // [m_local][n_local]
    __shared__ __align__(16) float Cs[32][68];   // [m_local][col]: 0..63 = h, 64 = x
    const int tid = threadIdx.x;
    const int tx = tid & 15, ty = tid >> 4;
    const float* xs = use_gx ? g_x : xsrc;
    const int xbs   = use_gx ? Nn : x_bstride;

    float acc[4][4];
    #pragma unroll
    for (int i = 0; i < 4; i++)
        #pragma unroll
        for (int j = 0; j < 4; j++) acc[i][j] = 0.f;
    float accx[4] = {0.f, 0.f, 0.f, 0.f};

    const float* Gbase = G + (size_t)k * Nn * Nn;
    for (int m0 = 0; m0 < Nn; m0 += 32) {
        // G tile: 64 rows x 32 m (stored transposed: Gs[m][n_local])
        {
            int r = tid >> 5, c = tid & 31;
            #pragma unroll
            for (int i = 0; i < 8; i++)
                Gs[c][r + i * 8] = Gbase[(size_t)(n0 + r + i * 8) * Nn + m0 + c];
        }
        // comb tile: 32 m x (64 h + 1 x)
        {
            int rr = tid >> 6, j = tid & 63;
            #pragma unroll
            for (int i = 0; i < 8; i++) {
                int r = rr + i * 4;
                Cs[r][j] = g_h[((size_t)b * Nn + m0 + r) * Hh + j];
            }
            if (tid < 32) Cs[tid][64] = xs[(size_t)b * xbs + m0 + tid];
        }
        __syncthreads();
        #pragma unroll
        for (int kk = 0; kk < 32; kk++) {
            float4 gv = *reinterpret_cast<const float4*>(&Gs[kk][ty * 4]);
            float4 cv = *reinterpret_cast<const float4*>(&Cs[kk][tx * 4]);
            float gvv[4] = {gv.x, gv.y, gv.z, gv.w};
            float cvv[4] = {cv.x, cv.y, cv.z, cv.w};
            #pragma unroll
            for (int i = 0; i < 4; i++)
                #pragma unroll
                for (int j = 0; j < 4; j++)
                    acc[i][j] += gvv[i] * cvv[j];
            if (tx == 0) {
                float xv = Cs[kk][64];
                #pragma unroll
                for (int i = 0; i < 4; i++) accx[i] += gvv[i] * xv;
            }
        }
        __syncthreads();
    }
    #pragma unroll
    for (int i = 0; i < 4; i++) {
        int n = n0 + ty * 4 + i;
        float* dst = g_sc + ((size_t)b * Nn + n) * SCP + k * DIN;
        #pragma unroll
        for (int j = 0; j < 4; j++) dst[1 + tx * 4 + j] = acc[i][j];
        if (tx == 0) dst[0] = accx[i];
    }
}

// ---------------- conv + LSTM: conv = sc @ W + bias; (h,c) update ----------------
// Block: 32 rows x 256 gate-cols, 256 threads, each owns 8 rows x 4 gates for one h.
__global__ void convlstm_kernel(int t, int per_batch,
                                const float* __restrict__ Wext,
                                const float* __restrict__ bext) {
    const int n0 = blockIdx.x * 32;
    const int b  = blockIdx.y;
    const int tid = threadIdx.x;
    const int hq = tid & 63;
    const int rg = tid >> 6;
    __shared__ float scs[32][17];
    __shared__ float wms[16][260];
    const float* Wb = per_batch ? (g_Wm + (size_t)(b * Tt + t) * WMC) : Wext;
    const float* bb = per_batch ? (g_bm + (size_t)(b * Tt + t) * G4) : bext;

    float acc[8][4];
    #pragma unroll
    for (int j = 0; j < 8; j++)
        #pragma unroll
        for (int g = 0; g < 4; g++) acc[j][g] = 0.f;

    for (int p0 = 0; p0 < Pp; p0 += 16) {
        {   // sc tile 32 x 16
            int r = tid >> 3, c = tid & 7;
            #pragma unroll
            for (int i = 0; i < 2; i++) {
                int p = p0 + c + i * 8;
                scs[r][c + i * 8] = (p < Pp) ? g_sc[((size_t)b * Nn + n0 + r) * SCP + p] : 0.f;
            }
        }
        {   // W tile 16 x 256
            #pragma unroll
            for (int pp = 0; pp < 16; pp++) {
                int p = p0 + pp;
                wms[pp][tid] = (p < Pp) ? Wb[(size_t)p * G4 + tid] : 0.f;
            }
        }
        __syncthreads();
        #pragma unroll
        for (int pp = 0; pp < 16; pp++) {
            float wv[4];
            #pragma unroll
            for (int g = 0; g < 4; g++) wv[g] = wms[pp][g * 64 + hq];
            #pragma unroll
            for (int j = 0; j < 8; j++) {
                float sv = scs[j * 4 + rg][pp];
                #pragma unroll
                for (int g = 0; g < 4; g++) acc[j][g] += sv * wv[g];
            }
        }
        __syncthreads();
    }
    float bi = bb[hq], bf = bb[64 + hq], bo = bb[128 + hq], bg = bb[192 + hq];
    #pragma unroll
    for (int j = 0; j < 8; j++) {
        int n = n0 + j * 4 + rg;
        float gi = acc[j][0] + bi;
        float gf = acc[j][1] + bf;
        float go = acc[j][2] + bo;
        float gg = acc[j][3] + bg;
        float iv = 1.f / (1.f + expf(-gi));
        float fv = 1.f / (1.f + expf(-gf));
        float ov = 1.f / (1.f + expf(-go));
        float gv = tanhf(gg);
        size_t idx = ((size_t)b * Nn + n) * Hh + hq;
        float cv = fv * g_c[idx] + iv * gv;
        g_c[idx] = cv;
        g_h[idx] = ov * tanhf(cv);
    }
}

// ---------------- decoder projection: out = h @ proj_w + proj_b ----------------
__global__ void proj_kernel(const float* __restrict__ proj_w,
                            const float* __restrict__ proj_b,
                            float* __restrict__ out, int s) {
    int row  = blockIdx.x * 8 + (threadIdx.x >> 5);   // [0, B*N)
    int lane = threadIdx.x & 31;
    const float* hrow = g_h + (size_t)row * Hh;
    float v = hrow[lane] * proj_w[lane] + hrow[lane + 32] * proj_w[lane + 32];
    #pragma unroll
    for (int o = 16; o; o >>= 1) v += __shfl_down_sync(0xffffffffu, v, o);
    if (lane == 0) {
        float r = v + proj_b[0];
        int b = row >> 10, n = row & 1023;
        out[((size_t)b * HOR + s) * Nn + n] = r;
        g_x[row] = r;
    }
}

// ---------------- launch ----------------
extern "C" void kernel_launch(void* const* d_in, const int* in_sizes, int n_in,
                              void* d_out, int out_size) {
    const float* G      = (const float*)d_in[0];
    const float* x_seq  = (const float*)d_in[1];
    const float* x_meta = (const float*)d_in[2];
    const float* lw1_w  = (const float*)d_in[3];
    const float* lw1_b  = (const float*)d_in[4];
    const float* lw2_w  = (const float*)d_in[5];
    const float* lw2_b  = (const float*)d_in[6];
    const float* lb1_w  = (const float*)d_in[7];
    const float* lb1_b  = (const float*)d_in[8];
    const float* lb2_w  = (const float*)d_in[9];
    const float* lb2_b  = (const float*)d_in[10];
    const float* dec_W  = (const float*)d_in[11];
    const float* dec_b  = (const float*)d_in[12];
    const float* proj_w = (const float*)d_in[13];
    const float* proj_b = (const float*)d_in[14];
    float* out = (float*)d_out;

    zero_hc_kernel<<<(Bz * Nn * Hh) / 256, 256>>>();
    meta1_kernel<<<BT, 128>>>(x_meta, lw1_w, lw1_b, lb1_w, lb1_b);
    meta2_kernel<<<dim3(WMC / 256, BT / 16), 256>>>(lw2_w, lw2_b);
    meta2b_kernel<<<BT, 256>>>(lb2_w, lb2_b);

    // encoder
    for (int t = 0; t < Tt; t++) {
        gcn_kernel<<<dim3(Nn / 64, Kk, Bz), 256>>>(G, x_seq + (size_t)t * Nn, Tt * Nn, 0);
        convlstm_kernel<<<dim3(Nn / 32, Bz), 256>>>(t, 1, nullptr, nullptr);
    }

    // decoder
    zero_x_kernel<<<(Bz * Nn) / 256, 256>>>();
    for (int s = 0; s < HOR; s++) {
        gcn_kernel<<<dim3(Nn / 64, Kk, Bz), 256>>>(G, nullptr, Nn, 1);
        convlstm_kernel<<<dim3(Nn / 32, Bz), 256>>>(0, 0, dec_W, dec_b);
        proj_kernel<<<(Bz * Nn) / 8, 256>>>(proj_w, proj_b, out, s);
    }
}

// round 12
// speedup vs baseline: 1.2759x; 1.2090x over previous
#include <cuda_runtime.h>
#include <cuda_bf16.h>
#include <math.h>
#include <stdint.h>

// ---------------- problem constants ----------------
#define Bz   64
#define Tt   12
#define Nn   1024
#define Hh   64
#define Mm   32
#define Kk   3
#define HOR  12
#define G4   256
#define Pp   195           // K*DIN = 3*65
#define KP   224           // P padded to multiple of 32
#define QT   72            // per-batch combT rows: 1 x + 64 h + 7 pad
#define NQ   (Bz*QT)       // 4608
#define BT   (Bz*Tt)       // 768
#define WMC  (Pp*G4)       // 49920
#define PADK 36            // smem row stride (floats) for 32-wide K tiles

// ---------------- device scratch (split big/small for tf32x3) ----------------
__device__ float g_Gb[(size_t)Kk*Nn*Nn];
__device__ float g_Gs[(size_t)Kk*Nn*Nn];
__device__ float g_cTb[(size_t)NQ*Nn];     // combT big: [q][m], q=b*72+col
__device__ float g_cTs[(size_t)NQ*Nn];
__device__ float g_scb[(size_t)Bz*Nn*KP];  // sc big: [b][n][p]
__device__ float g_scs[(size_t)Bz*Nn*KP];
__device__ float g_c[(size_t)Bz*Hh*Nn];    // cell state [b][hq][n]
__device__ float g_Wm[(size_t)BT*WMC];
__device__ float g_WmTb[(size_t)BT*G4*KP]; // [bt][gate][p]
__device__ float g_WmTs[(size_t)BT*G4*KP];
__device__ float g_dWb[G4*KP];
__device__ float g_dWs[G4*KP];
__device__ float g_bm[BT*G4];
__device__ float g_hid1[BT*64];
__device__ float g_hid2[BT*64];

// ---------------- helpers ----------------
__device__ __forceinline__ float tf32r(float x) {
    uint32_t u; asm("cvt.rna.tf32.f32 %0, %1;" : "=r"(u) : "f"(x));
    return __uint_as_float(u);
}

__device__ __forceinline__ void mma8(float c[4], const uint32_t a[4], const uint32_t b[2]) {
    asm volatile("mma.sync.aligned.m16n8k8.row.col.f32.tf32.tf32.f32 "
        "{%0,%1,%2,%3}, {%4,%5,%6,%7}, {%8,%9}, {%0,%1,%2,%3};"
        : "+f"(c[0]), "+f"(c[1]), "+f"(c[2]), "+f"(c[3])
        : "r"(a[0]), "r"(a[1]), "r"(a[2]), "r"(a[3]), "r"(b[0]), "r"(b[1]));
}

// ---------------- init / conversion ----------------
__global__ void zero_kernel() {
    size_t i = (size_t)blockIdx.x * 256 + threadIdx.x;
    g_scb[i] = 0.f; g_scs[i] = 0.f;                    // grid sized to sc
    if (i < (size_t)NQ * Nn)      { g_cTb[i] = 0.f; g_cTs[i] = 0.f; }
    if (i < (size_t)Bz * Hh * Nn) g_c[i] = 0.f;
}
__global__ void splitG_kernel(const float* __restrict__ G) {
    size_t i = (size_t)blockIdx.x * 256 + threadIdx.x;
    float v = G[i], vb = tf32r(v);
    g_Gb[i] = vb; g_Gs[i] = tf32r(v - vb);
}
__global__ void xrow_kernel(const float* __restrict__ xs, int t) {
    int g = blockIdx.x * 256 + threadIdx.x;
    int b = g >> 10, n = g & 1023;
    float v = xs[((size_t)(b * Tt + t)) * Nn + n], vb = tf32r(v);
    g_cTb[((size_t)(b * QT)) * Nn + n] = vb;
    g_cTs[((size_t)(b * QT)) * Nn + n] = tf32r(v - vb);
}
__global__ void zerox_kernel() {
    int g = blockIdx.x * 256 + threadIdx.x;
    int b = g >> 10, n = g & 1023;
    g_cTb[((size_t)(b * QT)) * Nn + n] = 0.f;
    g_cTs[((size_t)(b * QT)) * Nn + n] = 0.f;
}

// ---------------- meta MLPs ----------------
__global__ void meta1_kernel(const float* __restrict__ xm,
                             const float* __restrict__ lw1w, const float* __restrict__ lw1b,
                             const float* __restrict__ lb1w, const float* __restrict__ lb1b) {
    int bt = blockIdx.x;
    int o = threadIdx.x & 63;
    bool second = threadIdx.x >= 64;
    const float* W = second ? lb1w : lw1w;
    const float* bi = second ? lb1b : lw1b;
    float acc = bi[o];
    const float* x = xm + bt * Mm;
    #pragma unroll
    for (int m = 0; m < Mm; m++) acc += x[m] * W[m * 64 + o];
    acc = fmaxf(acc, 0.f);
    if (second) g_hid2[bt * 64 + o] = acc;
    else        g_hid1[bt * 64 + o] = acc;
}

__global__ void meta2_kernel(const float* __restrict__ lw2w, const float* __restrict__ lw2b) {
    int q0 = blockIdx.x * 256;
    int r0 = blockIdx.y * 16;
    __shared__ float hs[16][65];
    int tid = threadIdx.x;
    {
        int r = tid >> 6, c = tid & 63;
        #pragma unroll
        for (int i = 0; i < 4; i++)
            hs[r + i * 4][c] = g_hid1[(r0 + r + i * 4) * 64 + c];
    }
    __syncthreads();
    float acc[16];
    #pragma unroll
    for (int r = 0; r < 16; r++) acc[r] = 0.f;
    int q = q0 + tid;
    #pragma unroll 8
    for (int i = 0; i < 64; i++) {
        float w = lw2w[(size_t)i * WMC + q];
        #pragma unroll
        for (int r = 0; r < 16; r++) acc[r] += hs[r][i] * w;
    }
    float bv = lw2b[q];
    #pragma unroll
    for (int r = 0; r < 16; r++)
        g_Wm[(size_t)(r0 + r) * WMC + q] = acc[r] + bv;
}

__global__ void meta2b_kernel(const float* __restrict__ lb2w, const float* __restrict__ lb2b) {
    int bt = blockIdx.x, q = threadIdx.x;
    float acc = lb2b[q];
    const float* hrow = g_hid2 + bt * 64;
    #pragma unroll
    for (int i = 0; i < 64; i++) acc += hrow[i] * lb2w[i * G4 + q];
    g_bm[bt * G4 + q] = acc;
}

// Wm[p][g] -> WmT[g][p] split big/small, zero-padded to KP
__global__ void wmT_kernel() {
    __shared__ float s[32][257];
    int p0 = blockIdx.x * 32, bt = blockIdx.y, tid = threadIdx.x;
    for (int pi = 0; pi < 32; pi++) {
        int p = p0 + pi;
        s[pi][tid] = (p < Pp) ? g_Wm[(size_t)bt * WMC + (size_t)p * G4 + tid] : 0.f;
    }
    __syncthreads();
    float* db = g_WmTb + (size_t)bt * G4 * KP + (size_t)tid * KP + p0;
    float* ds = g_WmTs + (size_t)bt * G4 * KP + (size_t)tid * KP + p0;
    #pragma unroll
    for (int c = 0; c < 8; c++) {
        float x0 = s[c * 4 + 0][tid], x1 = s[c * 4 + 1][tid];
        float x2 = s[c * 4 + 2][tid], x3 = s[c * 4 + 3][tid];
        float4 vb = make_float4(tf32r(x0), tf32r(x1), tf32r(x2), tf32r(x3));
        float4 vs = make_float4(tf32r(x0 - vb.x), tf32r(x1 - vb.y), tf32r(x2 - vb.z), tf32r(x3 - vb.w));
        *reinterpret_cast<float4*>(db + c * 4) = vb;
        *reinterpret_cast<float4*>(ds + c * 4) = vs;
    }
}

__global__ void decWT_kernel(const float* __restrict__ dW) {
    int g = threadIdx.x;
    for (int p = 0; p < KP; p++) {
        float x = (p < Pp) ? dW[(size_t)p * G4 + g] : 0.f;
        float xb = tf32r(x);
        g_dWb[(size_t)g * KP + p] = xb;
        g_dWs[(size_t)g * KP + p] = tf32r(x - xb);
    }
}

// ---------------- GEMM1 (GCN): D[q][n] = sum_m combT[q][m] * G_k[n][m] ----------------
// CTA 128(q) x 128(n), 8 warps 2x4, warp tile 64x32, tf32x3 via mma.sync.
__global__ void __launch_bounds__(256) gemm1_kernel() {
    extern __shared__ float sm[];
    float* sAb = sm;            // 128*36
    float* sAs = sm + 4608;
    float* sBb = sm + 9216;
    float* sBs = sm + 13824;    // total 18432 floats = 73728 B
    const int tid = threadIdx.x, lane = tid & 31, wid = tid >> 5;
    const int wm = wid & 1, wn = wid >> 1;
    const int q0 = blockIdx.x * 128, nb = blockIdx.y * 128, k = blockIdx.z;
    const float* Gkb = g_Gb + (size_t)k * Nn * Nn;
    const float* Gks = g_Gs + (size_t)k * Nn * Nn;

    float c[4][4][4];
    #pragma unroll
    for (int mt = 0; mt < 4; mt++)
        #pragma unroll
        for (int nt = 0; nt < 4; nt++)
            #pragma unroll
            for (int i = 0; i < 4; i++) c[mt][nt][i] = 0.f;

    for (int m0 = 0; m0 < Nn; m0 += 32) {
        #pragma unroll
        for (int i = 0; i < 4; i++) {          // A tile 128x32 (big+small)
            int idx = tid + 256 * i;
            int r = idx >> 3, c4 = (idx & 7) * 4;
            size_t src = (size_t)(q0 + r) * Nn + m0 + c4;
            *reinterpret_cast<float4*>(&sAb[r * PADK + c4]) = *reinterpret_cast<const float4*>(&g_cTb[src]);
            *reinterpret_cast<float4*>(&sAs[r * PADK + c4]) = *reinterpret_cast<const float4*>(&g_cTs[src]);
        }
        #pragma unroll
        for (int i = 0; i < 4; i++) {          // B tile 128x32 (big+small)
            int idx = tid + 256 * i;
            int r = idx >> 3, c4 = (idx & 7) * 4;
            size_t src = (size_t)(nb + r) * Nn + m0 + c4;
            *reinterpret_cast<float4*>(&sBb[r * PADK + c4]) = *reinterpret_cast<const float4*>(&Gkb[src]);
            *reinterpret_cast<float4*>(&sBs[r * PADK + c4]) = *reinterpret_cast<const float4*>(&Gks[src]);
        }
        __syncthreads();
        #pragma unroll
        for (int ks = 0; ks < 4; ks++) {
            const int ak = ks * 8 + (lane & 3);
            const int ar = wm * 64 + (lane >> 2);
            uint32_t Ab[4][4], As[4][4];
            #pragma unroll
            for (int mt = 0; mt < 4; mt++) {
                int r = ar + mt * 16;
                Ab[mt][0] = __float_as_uint(sAb[r * PADK + ak]);
                Ab[mt][1] = __float_as_uint(sAb[(r + 8) * PADK + ak]);
                Ab[mt][2] = __float_as_uint(sAb[r * PADK + ak + 4]);
                Ab[mt][3] = __float_as_uint(sAb[(r + 8) * PADK + ak + 4]);
                As[mt][0] = __float_as_uint(sAs[r * PADK + ak]);
                As[mt][1] = __float_as_uint(sAs[(r + 8) * PADK + ak]);
                As[mt][2] = __float_as_uint(sAs[r * PADK + ak + 4]);
                As[mt][3] = __float_as_uint(sAs[(r + 8) * PADK + ak + 4]);
            }
            #pragma unroll
            for (int nt = 0; nt < 4; nt++) {
                int bc = wn * 32 + nt * 8 + (lane >> 2);
                uint32_t Bb[2], Bs[2];
                Bb[0] = __float_as_uint(sBb[bc * PADK + ak]);
                Bb[1] = __float_as_uint(sBb[bc * PADK + ak + 4]);
                Bs[0] = __float_as_uint(sBs[bc * PADK + ak]);
                Bs[1] = __float_as_uint(sBs[bc * PADK + ak + 4]);
                #pragma unroll
                for (int mt = 0; mt < 4; mt++) {
                    mma8(c[mt][nt], Ab[mt], Bb);
                    mma8(c[mt][nt], As[mt], Bb);
                    mma8(c[mt][nt], Ab[mt], Bs);
                }
            }
        }
        __syncthreads();
    }
    // epilogue: q -> (b, col, p), write split sc
    #pragma unroll
    for (int mt = 0; mt < 4; mt++) {
        #pragma unroll
        for (int rh = 0; rh < 2; rh++) {
            int q = q0 + wm * 64 + mt * 16 + (lane >> 2) + rh * 8;
            int b = q / QT, col = q - b * QT;
            if (col >= 65) continue;
            int p = k * 65 + col;
            size_t base = (size_t)b * Nn * KP + p;
            #pragma unroll
            for (int nt = 0; nt < 4; nt++) {
                #pragma unroll
                for (int ci = 0; ci < 2; ci++) {
                    int n = nb + wn * 32 + nt * 8 + 2 * (lane & 3) + ci;
                    float v = c[mt][nt][rh * 2 + ci];
                    float vb = tf32r(v);
                    g_scb[base + (size_t)n * KP] = vb;
                    g_scs[base + (size_t)n * KP] = tf32r(v - vb);
                }
            }
        }
    }
}

// ---------------- GEMM2 + LSTM: D[n][g] = sum_p sc[n][p] * WmT[g][p]; update c,h -------
// CTA 128(n) x 256(gates), 8 warps 2x4, warp tile 64x64, conv staged via smem.
#define CPAD 261
__global__ void __launch_bounds__(256) gemm2_kernel(int t, int per_batch,
                                                    const float* __restrict__ bext) {
    extern __shared__ float sm[];
    float* sAb = sm;            // 128*36 = 4608
    float* sAs = sm + 4608;
    float* sBb = sm + 9216;     // 256*36 = 9216
    float* sBs = sm + 18432;    // operand end: 27648
    float* conv = sm;           // reuse: 128*261 = 33408
    float* bias = sm + 33408;   // 256 -> total 33664 floats = 134656 B
    const int tid = threadIdx.x, lane = tid & 31, wid = tid >> 5;
    const int wm = wid & 1, wn = wid >> 1;
    const int b = blockIdx.y, n0 = blockIdx.x * 128;
    const float *Wtb, *Wts, *bb;
    if (per_batch) {
        size_t o = (size_t)(b * Tt + t) * G4 * KP;
        Wtb = g_WmTb + o; Wts = g_WmTs + o; bb = g_bm + (b * Tt + t) * G4;
    } else { Wtb = g_dWb; Wts = g_dWs; bb = bext; }
    bias[tid] = bb[tid];

    float c[4][8][4];
    #pragma unroll
    for (int mt = 0; mt < 4; mt++)
        #pragma unroll
        for (int nt = 0; nt < 8; nt++)
            #pragma unroll
            for (int i = 0; i < 4; i++) c[mt][nt][i] = 0.f;

    const float* scb = g_scb + (size_t)b * Nn * KP;
    const float* scs = g_scs + (size_t)b * Nn * KP;

    for (int p0 = 0; p0 < KP; p0 += 32) {
        #pragma unroll
        for (int i = 0; i < 4; i++) {          // A: sc 128x32
            int idx = tid + 256 * i;
            int r = idx >> 3, c4 = (idx & 7) * 4;
            size_t src = (size_t)(n0 + r) * KP + p0 + c4;
            *reinterpret_cast<float4*>(&sAb[r * PADK + c4]) = *reinterpret_cast<const float4*>(&scb[src]);
            *reinterpret_cast<float4*>(&sAs[r * PADK + c4]) = *reinterpret_cast<const float4*>(&scs[src]);
        }
        #pragma unroll
        for (int i = 0; i < 8; i++) {          // B: WmT 256x32
            int idx = tid + 256 * i;
            int r = idx >> 3, c4 = (idx & 7) * 4;
            size_t src = (size_t)r * KP + p0 + c4;
            *reinterpret_cast<float4*>(&sBb[r * PADK + c4]) = *reinterpret_cast<const float4*>(&Wtb[src]);
            *reinterpret_cast<float4*>(&sBs[r * PADK + c4]) = *reinterpret_cast<const float4*>(&Wts[src]);
        }
        __syncthreads();
        #pragma unroll
        for (int ks = 0; ks < 4; ks++) {
            const int ak = ks * 8 + (lane & 3);
            const int ar = wm * 64 + (lane >> 2);
            uint32_t Ab[4][4], As[4][4];
            #pragma unroll
            for (int mt = 0; mt < 4; mt++) {
                int r = ar + mt * 16;
                Ab[mt][0] = __float_as_uint(sAb[r * PADK + ak]);
                Ab[mt][1] = __float_as_uint(sAb[(r + 8) * PADK + ak]);
                Ab[mt][2] = __float_as_uint(sAb[r * PADK + ak + 4]);
                Ab[mt][3] = __float_as_uint(sAb[(r + 8) * PADK + ak + 4]);
                As[mt][0] = __float_as_uint(sAs[r * PADK + ak]);
                As[mt][1] = __float_as_uint(sAs[(r + 8) * PADK + ak]);
                As[mt][2] = __float_as_uint(sAs[r * PADK + ak + 4]);
                As[mt][3] = __float_as_uint(sAs[(r + 8) * PADK + ak + 4]);
            }
            #pragma unroll
            for (int nt = 0; nt < 8; nt++) {
                int bc = wn * 64 + nt * 8 + (lane >> 2);
                uint32_t Bb[2], Bs[2];
                Bb[0] = __float_as_uint(sBb[bc * PADK + ak]);
                Bb[1] = __float_as_uint(sBb[bc * PADK + ak + 4]);
                Bs[0] = __float_as_uint(sBs[bc * PADK + ak]);
                Bs[1] = __float_as_uint(sBs[bc * PADK + ak + 4]);
                #pragma unroll
                for (int mt = 0; mt < 4; mt++) {
                    mma8(c[mt][nt], Ab[mt], Bb);
                    mma8(c[mt][nt], As[mt], Bb);
                    mma8(c[mt][nt], Ab[mt], Bs);
                }
            }
        }
        __syncthreads();
    }

    // stage conv into smem (overlaps operand region; synced above)
    #pragma unroll
    for (int mt = 0; mt < 4; mt++) {
        #pragma unroll
        for (int nt = 0; nt < 8; nt++) {
            #pragma unroll
            for (int i = 0; i < 4; i++) {
                int row = wm * 64 + mt * 16 + (lane >> 2) + (i >> 1) * 8;
                int gate = wn * 64 + nt * 8 + 2 * (lane & 3) + (i & 1);
                conv[row * CPAD + gate] = c[mt][nt][i];
            }
        }
    }
    __syncthreads();

    // LSTM update: each warp owns 8 hq values, lanes sweep n (coalesced)
    #pragma unroll
    for (int hh = 0; hh < 8; hh++) {
        int hq = wid * 8 + hh;
        float bi_ = bias[hq], bf_ = bias[64 + hq], bo_ = bias[128 + hq], bg_ = bias[192 + hq];
        #pragma unroll
        for (int rr = 0; rr < 4; rr++) {
            int row = lane + rr * 32;
            int n = n0 + row;
            float gi = conv[row * CPAD + hq] + bi_;
            float gf = conv[row * CPAD + 64 + hq] + bf_;
            float go = conv[row * CPAD + 128 + hq] + bo_;
            float gg = conv[row * CPAD + 192 + hq] + bg_;
            float iv = 1.f / (1.f + __expf(-gi));
            float fv = 1.f / (1.f + __expf(-gf));
            float ov = 1.f / (1.f + __expf(-go));
            float gv = tanhf(gg);
            size_t ci = ((size_t)(b * Hh + hq)) * Nn + n;
            float cv = fv * g_c[ci] + iv * gv;
            g_c[ci] = cv;
            float hv = ov * tanhf(cv);
            float hb2 = tf32r(hv);
            size_t qi = ((size_t)(b * QT + 1 + hq)) * Nn + n;
            g_cTb[qi] = hb2;
            g_cTs[qi] = tf32r(hv - hb2);
        }
    }
}

// ---------------- decoder projection ----------------
__global__ void proj_kernel(const float* __restrict__ pw, const float* __restrict__ pb,
                            float* __restrict__ out, int s) {
    int g = blockIdx.x * 256 + threadIdx.x;
    int b = g >> 10, n = g & 1023;
    const float* hb = g_cTb + ((size_t)(b * QT + 1)) * Nn + n;
    const float* hs = g_cTs + ((size_t)(b * QT + 1)) * Nn + n;
    float acc = pb[0];
    #pragma unroll
    for (int hq = 0; hq < 64; hq++)
        acc += (hb[(size_t)hq * Nn] + hs[(size_t)hq * Nn]) * pw[hq];
    out[((size_t)b * HOR + s) * Nn + n] = acc;
    float xb = tf32r(acc);
    g_cTb[((size_t)(b * QT)) * Nn + n] = xb;
    g_cTs[((size_t)(b * QT)) * Nn + n] = tf32r(acc - xb);
}

// ---------------- launch ----------------
#define SMEM1 (18432 * 4)
#define SMEM2 (33664 * 4)

extern "C" void kernel_launch(void* const* d_in, const int* in_sizes, int n_in,
                              void* d_out, int out_size) {
    const float* G      = (const float*)d_in[0];
    const float* x_seq  = (const float*)d_in[1];
    const float* x_meta = (const float*)d_in[2];
    const float* lw1_w  = (const float*)d_in[3];
    const float* lw1_b  = (const float*)d_in[4];
    const float* lw2_w  = (const float*)d_in[5];
    const float* lw2_b  = (const float*)d_in[6];
    const float* lb1_w  = (const float*)d_in[7];
    const float* lb1_b  = (const float*)d_in[8];
    const float* lb2_w  = (const float*)d_in[9];
    const float* lb2_b  = (const float*)d_in[10];
    const float* dec_W  = (const float*)d_in[11];
    const float* dec_b  = (const float*)d_in[12];
    const float* proj_w = (const float*)d_in[13];
    const float* proj_b = (const float*)d_in[14];
    float* out = (float*)d_out;

    static int attr_done = 0;
    if (!attr_done) {
        cudaFuncSetAttribute(gemm1_kernel, cudaFuncAttributeMaxDynamicSharedMemorySize, SMEM1);
        cudaFuncSetAttribute(gemm2_kernel, cudaFuncAttributeMaxDynamicSharedMemorySize, SMEM2);
        attr_done = 1;
    }

    zero_kernel<<<(Bz * Nn * KP) / 256, 256>>>();
    splitG_kernel<<<(Kk * Nn * Nn) / 256, 256>>>(G);
    meta1_kernel<<<BT, 128>>>(x_meta, lw1_w, lw1_b, lb1_w, lb1_b);
    meta2_kernel<<<dim3(WMC / 256, BT / 16), 256>>>(lw2_w, lw2_b);
    meta2b_kernel<<<BT, 256>>>(lb2_w, lb2_b);
    wmT_kernel<<<dim3(KP / 32, BT), 256>>>();
    decWT_kernel<<<1, 256>>>(dec_W);

    // encoder
    for (int t = 0; t < Tt; t++) {
        xrow_kernel<<<(Bz * Nn) / 256, 256>>>(x_seq, t);
        gemm1_kernel<<<dim3(NQ / 128, Nn / 128, Kk), 256, SMEM1>>>();
        gemm2_kernel<<<dim3(Nn / 128, Bz), 256, SMEM2>>>(t, 1, nullptr);
    }

    // decoder
    zerox_kernel<<<(Bz * Nn) / 256, 256>>>();
    for (int s = 0; s < HOR; s++) {
        gemm1_kernel<<<dim3(NQ / 128, Nn / 128, Kk), 256, SMEM1>>>();
        gemm2_kernel<<<dim3(Nn / 128, Bz), 256, SMEM2>>>(0, 0, dec_b);
        proj_kernel<<<(Bz * Nn) / 256, 256>>>(proj_w, proj_b, out, s);
    }
}

// round 13
// speedup vs baseline: 2.7678x; 2.1692x over previous
#include <cuda_runtime.h>
#include <cuda_fp16.h>
#include <cuda_bf16.h>
#include <math.h>
#include <stdint.h>

// ---------------- problem constants ----------------
#define Bz   64
#define Tt   12
#define Nn   1024
#define Hh   64
#define Mm   32
#define Kk   3
#define HOR  12
#define G4   256
#define Pp   195           // K*DIN = 3*65
#define KP   224           // P padded to multiple of 32
#define QT   72            // per-batch combT rows: 1 x + 64 h + 7 pad
#define NQ   (Bz*QT)       // 4608
#define BT   (Bz*Tt)       // 768
#define WMC  (Pp*G4)       // 49920

#define PADH  40           // smem halves per 32-k row (bank-perfect)
#define TILEA (128*PADH)   // 5120 halves per array per stage
#define STAGE (4*TILEA)    // Ah Al Bh Bl
#define SMEMB (2*STAGE*2)  // bytes: 2 stages * halves*2 = 81920
#define CPAD2 132

// ---------------- device scratch (fp16 hi/lo split) ----------------
__device__ __align__(16) __half g_Gh[(size_t)Kk*Nn*Nn];
__device__ __align__(16) __half g_Gl[(size_t)Kk*Nn*Nn];
__device__ __align__(16) __half g_cTh[(size_t)NQ*Nn];     // combT [q][m]
__device__ __align__(16) __half g_cTl[(size_t)NQ*Nn];
__device__ __align__(16) __half g_sch[(size_t)Bz*Nn*KP];  // sc [b][n][p]
__device__ __align__(16) __half g_scl[(size_t)Bz*Nn*KP];
__device__ __align__(16) __half g_WmTh[(size_t)BT*G4*KP]; // [bt][pg][p]
__device__ __align__(16) __half g_WmTl[(size_t)BT*G4*KP];
__device__ __align__(16) __half g_dWh[G4*KP];
__device__ __align__(16) __half g_dWl[G4*KP];
__device__ float g_c[(size_t)Bz*Hh*Nn];                   // cell [b][hq][n]
__device__ float g_Wm[(size_t)BT*WMC];
__device__ float g_bm[BT*G4];
__device__ float g_hid1[BT*64];
__device__ float g_hid2[BT*64];

// ---------------- helpers ----------------
__device__ __forceinline__ uint32_t smem_u32(const void* p) {
    uint32_t a;
    asm("{ .reg .u64 t; cvta.to.shared.u64 t, %1; cvt.u32.u64 %0, t; }" : "=r"(a) : "l"(p));
    return a;
}
__device__ __forceinline__ void cpa16(uint32_t dst, const void* src) {
    asm volatile("cp.async.cg.shared.global [%0], [%1], 16;" :: "r"(dst), "l"(src));
}
#define CP_COMMIT() asm volatile("cp.async.commit_group;" ::: "memory")
#define CP_WAIT1()  asm volatile("cp.async.wait_group 1;" ::: "memory")
#define CP_WAIT0()  asm volatile("cp.async.wait_group 0;" ::: "memory")

__device__ __forceinline__ void mma16(float c[4], const uint32_t a[4], const uint32_t b[2]) {
    asm volatile("mma.sync.aligned.m16n8k16.row.col.f32.f16.f16.f32 "
        "{%0,%1,%2,%3}, {%4,%5,%6,%7}, {%8,%9}, {%0,%1,%2,%3};"
        : "+f"(c[0]), "+f"(c[1]), "+f"(c[2]), "+f"(c[3])
        : "r"(a[0]), "r"(a[1]), "r"(a[2]), "r"(a[3]), "r"(b[0]), "r"(b[1]));
}

__device__ __forceinline__ void splitw(float x, __half& hi, __half& lo) {
    hi = __float2half(x);
    lo = __float2half(x - __half2float(hi));
}

// shared fragment+mma block: one 32-k chunk, warp tile 64x32, fp16x3
__device__ __forceinline__ void frag_mma_block(
    const __half* Ah, const __half* Al, const __half* Bh, const __half* Bl,
    int lane, int wm, int wn, float c[4][4][4])
{
    const int g = lane >> 2;
    #pragma unroll
    for (int ks = 0; ks < 2; ks++) {
        const int kb = ks * 16 + 2 * (lane & 3);
        uint32_t ah[4][4], al[4][4];
        #pragma unroll
        for (int mt = 0; mt < 4; mt++) {
            int r = wm * 64 + mt * 16 + g;
            ah[mt][0] = *(const uint32_t*)&Ah[r * PADH + kb];
            ah[mt][1] = *(const uint32_t*)&Ah[(r + 8) * PADH + kb];
            ah[mt][2] = *(const uint32_t*)&Ah[r * PADH + kb + 8];
            ah[mt][3] = *(const uint32_t*)&Ah[(r + 8) * PADH + kb + 8];
            al[mt][0] = *(const uint32_t*)&Al[r * PADH + kb];
            al[mt][1] = *(const uint32_t*)&Al[(r + 8) * PADH + kb];
            al[mt][2] = *(const uint32_t*)&Al[r * PADH + kb + 8];
            al[mt][3] = *(const uint32_t*)&Al[(r + 8) * PADH + kb + 8];
        }
        #pragma unroll
        for (int nt = 0; nt < 4; nt++) {
            int bc = wn * 32 + nt * 8 + g;
            uint32_t bh[2], bl[2];
            bh[0] = *(const uint32_t*)&Bh[bc * PADH + kb];
            bh[1] = *(const uint32_t*)&Bh[bc * PADH + kb + 8];
            bl[0] = *(const uint32_t*)&Bl[bc * PADH + kb];
            bl[1] = *(const uint32_t*)&Bl[bc * PADH + kb + 8];
            #pragma unroll
            for (int mt = 0; mt < 4; mt++) {
                mma16(c[mt][nt], ah[mt], bh);
                mma16(c[mt][nt], al[mt], bh);
                mma16(c[mt][nt], ah[mt], bl);
            }
        }
    }
}

// ---------------- init / conversion ----------------
__global__ void zero_kernel() {
    size_t i = (size_t)blockIdx.x * 256 + threadIdx.x;
    __half z = __float2half(0.f);
    g_sch[i] = z; g_scl[i] = z;
    if (i < (size_t)NQ * Nn)      { g_cTh[i] = z; g_cTl[i] = z; }
    if (i < (size_t)Bz * Hh * Nn) g_c[i] = 0.f;
}
__global__ void splitG_kernel(const float* __restrict__ G) {
    size_t i = (size_t)blockIdx.x * 256 + threadIdx.x;
    __half hi, lo; splitw(G[i], hi, lo);
    g_Gh[i] = hi; g_Gl[i] = lo;
}
__global__ void xrow_kernel(const float* __restrict__ xs, int t) {
    int g = blockIdx.x * 256 + threadIdx.x;
    int b = g >> 10, n = g & 1023;
    __half hi, lo; splitw(xs[((size_t)(b * Tt + t)) * Nn + n], hi, lo);
    size_t o = ((size_t)(b * QT)) * Nn + n;
    g_cTh[o] = hi; g_cTl[o] = lo;
}
__global__ void zerox_kernel() {
    int g = blockIdx.x * 256 + threadIdx.x;
    int b = g >> 10, n = g & 1023;
    size_t o = ((size_t)(b * QT)) * Nn + n;
    __half z = __float2half(0.f);
    g_cTh[o] = z; g_cTl[o] = z;
}

// ---------------- meta MLPs ----------------
__global__ void meta1_kernel(const float* __restrict__ xm,
                             const float* __restrict__ lw1w, const float* __restrict__ lw1b,
                             const float* __restrict__ lb1w, const float* __restrict__ lb1b) {
    int bt = blockIdx.x;
    int o = threadIdx.x & 63;
    bool second = threadIdx.x >= 64;
    const float* W = second ? lb1w : lw1w;
    const float* bi = second ? lb1b : lw1b;
    float acc = bi[o];
    const float* x = xm + bt * Mm;
    #pragma unroll
    for (int m = 0; m < Mm; m++) acc += x[m] * W[m * 64 + o];
    acc = fmaxf(acc, 0.f);
    if (second) g_hid2[bt * 64 + o] = acc;
    else        g_hid1[bt * 64 + o] = acc;
}

__global__ void meta2_kernel(const float* __restrict__ lw2w, const float* __restrict__ lw2b) {
    int q0 = blockIdx.x * 256;
    int r0 = blockIdx.y * 16;
    __shared__ float hs[16][65];
    int tid = threadIdx.x;
    {
        int r = tid >> 6, c = tid & 63;
        #pragma unroll
        for (int i = 0; i < 4; i++)
            hs[r + i * 4][c] = g_hid1[(r0 + r + i * 4) * 64 + c];
    }
    __syncthreads();
    float acc[16];
    #pragma unroll
    for (int r = 0; r < 16; r++) acc[r] = 0.f;
    int q = q0 + tid;
    #pragma unroll 8
    for (int i = 0; i < 64; i++) {
        float w = lw2w[(size_t)i * WMC + q];
        #pragma unroll
        for (int r = 0; r < 16; r++) acc[r] += hs[r][i] * w;
    }
    float bv = lw2b[q];
    #pragma unroll
    for (int r = 0; r < 16; r++)
        g_Wm[(size_t)(r0 + r) * WMC + q] = acc[r] + bv;
}

__global__ void meta2b_kernel(const float* __restrict__ lb2w, const float* __restrict__ lb2b) {
    int bt = blockIdx.x, q = threadIdx.x;
    float acc = lb2b[q];
    const float* hrow = g_hid2 + bt * 64;
    #pragma unroll
    for (int i = 0; i < 64; i++) acc += hrow[i] * lb2w[i * G4 + q];
    g_bm[bt * G4 + q] = acc;
}

// Wm[p][g] -> WmT[pg][p] fp16 split, gate-permuted: pg=(hq>>5)*128+(hq&31)*4+gt
__global__ void wmT_kernel() {
    __shared__ float s[32][257];
    int p0 = blockIdx.x * 32, bt = blockIdx.y, tid = threadIdx.x;
    for (int pi = 0; pi < 32; pi++) {
        int p = p0 + pi;
        s[pi][tid] = (p < Pp) ? g_Wm[(size_t)bt * WMC + (size_t)p * G4 + tid] : 0.f;
    }
    __syncthreads();
    int gt = tid >> 6, hq = tid & 63;
    int gp = (hq >> 5) * 128 + (hq & 31) * 4 + gt;
    __half* dh = g_WmTh + (size_t)bt * G4 * KP + (size_t)gp * KP + p0;
    __half* dl = g_WmTl + (size_t)bt * G4 * KP + (size_t)gp * KP + p0;
    #pragma unroll
    for (int c = 0; c < 32; c++) {
        __half hi, lo; splitw(s[c][tid], hi, lo);
        dh[c] = hi; dl[c] = lo;
    }
}

__global__ void decWT_kernel(const float* __restrict__ dW) {
    int g = threadIdx.x;
    int gt = g >> 6, hq = g & 63;
    int gp = (hq >> 5) * 128 + (hq & 31) * 4 + gt;
    for (int p = 0; p < KP; p++) {
        float x = (p < Pp) ? dW[(size_t)p * G4 + g] : 0.f;
        __half hi, lo; splitw(x, hi, lo);
        g_dWh[(size_t)gp * KP + p] = hi;
        g_dWl[(size_t)gp * KP + p] = lo;
    }
}

// ---------------- GEMM1 (GCN): D[q][n] = sum_m combT[q][m] * G_k[n][m] ----------------
__global__ void __launch_bounds__(256, 2) gemm1_kernel() {
    extern __shared__ __half sh[];
    uint32_t sbase = smem_u32(sh);
    const int tid = threadIdx.x, lane = tid & 31, wid = tid >> 5;
    const int wm = wid & 1, wn = wid >> 1;
    const int q0 = blockIdx.x * 128, nb = blockIdx.y * 128, k = blockIdx.z;
    const size_t Gbase = (size_t)k * Nn * Nn;

    float c[4][4][4];
    #pragma unroll
    for (int mt = 0; mt < 4; mt++)
        #pragma unroll
        for (int nt = 0; nt < 4; nt++)
            #pragma unroll
            for (int i = 0; i < 4; i++) c[mt][nt][i] = 0.f;

    auto load_chunk = [&](int ch, int st) {
        int m0 = ch * 32;
        #pragma unroll
        for (int i = 0; i < 2; i++) {
            int idx = tid + 256 * i;
            int r = idx >> 2, c8 = (idx & 3) * 8;
            uint32_t d = sbase + (uint32_t)(st * STAGE + r * PADH + c8) * 2;
            size_t sA = (size_t)(q0 + r) * Nn + m0 + c8;
            cpa16(d, g_cTh + sA);
            cpa16(d + TILEA * 2, g_cTl + sA);
            size_t sB = Gbase + (size_t)(nb + r) * Nn + m0 + c8;
            cpa16(d + 2 * TILEA * 2, g_Gh + sB);
            cpa16(d + 3 * TILEA * 2, g_Gl + sB);
        }
        CP_COMMIT();
    };

    load_chunk(0, 0);
    for (int ch = 0; ch < 32; ch++) {
        if (ch + 1 < 32) { load_chunk(ch + 1, (ch + 1) & 1); CP_WAIT1(); }
        else             { CP_WAIT0(); }
        __syncthreads();
        const __half* Ah = sh + (ch & 1) * STAGE;
        frag_mma_block(Ah, Ah + TILEA, Ah + 2 * TILEA, Ah + 3 * TILEA, lane, wm, wn, c);
        __syncthreads();
    }

    // epilogue: q -> (b, col, p); write split sc halves
    #pragma unroll
    for (int mt = 0; mt < 4; mt++) {
        #pragma unroll
        for (int rh = 0; rh < 2; rh++) {
            int q = q0 + wm * 64 + mt * 16 + (lane >> 2) + rh * 8;
            int b = q / QT, col = q - b * QT;
            if (col >= 65) continue;
            int p = k * 65 + col;
            size_t base = (size_t)(b * Nn) * KP + p;
            #pragma unroll
            for (int nt = 0; nt < 4; nt++) {
                #pragma unroll
                for (int ci = 0; ci < 2; ci++) {
                    int n = nb + wn * 32 + nt * 8 + 2 * (lane & 3) + ci;
                    __half hi, lo; splitw(c[mt][nt][rh * 2 + ci], hi, lo);
                    g_sch[base + (size_t)n * KP] = hi;
                    g_scl[base + (size_t)n * KP] = lo;
                }
            }
        }
    }
}

// ---------------- GEMM2 + LSTM: D[n][pg] over 128 gates (hblk), fused update -------
__global__ void __launch_bounds__(256, 2) gemm2_kernel(int t, int per_batch,
                                                       const float* __restrict__ bext) {
    extern __shared__ __half sh[];
    uint32_t sbase = smem_u32(sh);
    const int tid = threadIdx.x, lane = tid & 31, wid = tid >> 5;
    const int wm = wid & 1, wn = wid >> 1;
    const int n0 = blockIdx.x * 128, b = blockIdx.y, hblk = blockIdx.z;
    const int gblk = hblk * 128;
    const __half *Wth, *Wtl; const float* bb;
    if (per_batch) {
        size_t o = (size_t)(b * Tt + t) * G4 * KP;
        Wth = g_WmTh + o; Wtl = g_WmTl + o; bb = g_bm + (b * Tt + t) * G4;
    } else { Wth = g_dWh; Wtl = g_dWl; bb = bext; }

    float c[4][4][4];
    #pragma unroll
    for (int mt = 0; mt < 4; mt++)
        #pragma unroll
        for (int nt = 0; nt < 4; nt++)
            #pragma unroll
            for (int i = 0; i < 4; i++) c[mt][nt][i] = 0.f;

    auto load_chunk = [&](int ch, int st) {
        int p0 = ch * 32;
        #pragma unroll
        for (int i = 0; i < 2; i++) {
            int idx = tid + 256 * i;
            int r = idx >> 2, c8 = (idx & 3) * 8;
            uint32_t d = sbase + (uint32_t)(st * STAGE + r * PADH + c8) * 2;
            size_t sA = (size_t)(b * Nn + n0 + r) * KP + p0 + c8;
            cpa16(d, g_sch + sA);
            cpa16(d + TILEA * 2, g_scl + sA);
            size_t sB = (size_t)(gblk + r) * KP + p0 + c8;
            cpa16(d + 2 * TILEA * 2, Wth + sB);
            cpa16(d + 3 * TILEA * 2, Wtl + sB);
        }
        CP_COMMIT();
    };

    load_chunk(0, 0);
    for (int ch = 0; ch < 7; ch++) {
        if (ch + 1 < 7) { load_chunk(ch + 1, (ch + 1) & 1); CP_WAIT1(); }
        else            { CP_WAIT0(); }
        __syncthreads();
        const __half* Ah = sh + (ch & 1) * STAGE;
        frag_mma_block(Ah, Ah + TILEA, Ah + 2 * TILEA, Ah + 3 * TILEA, lane, wm, wn, c);
        __syncthreads();
    }

    // stage conv[n_local][pg] in smem (reuses pipeline buffers)
    float* conv = reinterpret_cast<float*>(sh);
    #pragma unroll
    for (int mt = 0; mt < 4; mt++) {
        #pragma unroll
        for (int nt = 0; nt < 4; nt++) {
            #pragma unroll
            for (int i = 0; i < 4; i++) {
                int row = wm * 64 + mt * 16 + (lane >> 2) + (i >> 1) * 8;
                int pg = wn * 32 + nt * 8 + 2 * (lane & 3) + (i & 1);
                conv[row * CPAD2 + pg] = c[mt][nt][i];
            }
        }
    }
    __syncthreads();

    // fused LSTM: hq = hblk*32 + hl; gates at conv[row][hl*4 + {0,1,2,3}]
    #pragma unroll
    for (int u = 0; u < 4; u++) {
        int hl = wid + u * 8;
        int hq = hblk * 32 + hl;
        float bi_ = bb[hq], bf_ = bb[64 + hq], bo_ = bb[128 + hq], bg_ = bb[192 + hq];
        #pragma unroll
        for (int i = 0; i < 4; i++) {
            int row = lane + i * 32;
            int n = n0 + row;
            float4 gv4 = *reinterpret_cast<const float4*>(&conv[row * CPAD2 + hl * 4]);
            float gi = gv4.x + bi_, gf = gv4.y + bf_, go = gv4.z + bo_, gg = gv4.w + bg_;
            float iv = 1.f / (1.f + __expf(-gi));
            float fv = 1.f / (1.f + __expf(-gf));
            float ov = 1.f / (1.f + __expf(-go));
            float gvv = tanhf(gg);
            size_t ci = ((size_t)(b * Hh + hq)) * Nn + n;
            float cv = fv * g_c[ci] + iv * gvv;
            g_c[ci] = cv;
            float hv = ov * tanhf(cv);
            __half hi2, lo2; splitw(hv, hi2, lo2);
            size_t qi = ((size_t)(b * QT + 1 + hq)) * Nn + n;
            g_cTh[qi] = hi2; g_cTl[qi] = lo2;
        }
    }
}

// ---------------- decoder projection ----------------
__global__ void proj_kernel(const float* __restrict__ pw, const float* __restrict__ pb,
                            float* __restrict__ out, int s) {
    int g = blockIdx.x * 256 + threadIdx.x;
    int b = g >> 10, n = g & 1023;
    const __half* hh = g_cTh + ((size_t)(b * QT + 1)) * Nn + n;
    const __half* hl = g_cTl + ((size_t)(b * QT + 1)) * Nn + n;
    float acc = pb[0];
    #pragma unroll
    for (int hq = 0; hq < 64; hq++)
        acc += (__half2float(hh[(size_t)hq * Nn]) + __half2float(hl[(size_t)hq * Nn])) * pw[hq];
    out[((size_t)b * HOR + s) * Nn + n] = acc;
    __half hi, lo; splitw(acc, hi, lo);
    size_t o = ((size_t)(b * QT)) * Nn + n;
    g_cTh[o] = hi; g_cTl[o] = lo;
}

// ---------------- launch ----------------
extern "C" void kernel_launch(void* const* d_in, const int* in_sizes, int n_in,
                              void* d_out, int out_size) {
    const float* G      = (const float*)d_in[0];
    const float* x_seq  = (const float*)d_in[1];
    const float* x_meta = (const float*)d_in[2];
    const float* lw1_w  = (const float*)d_in[3];
    const float* lw1_b  = (const float*)d_in[4];
    const float* lw2_w  = (const float*)d_in[5];
    const float* lw2_b  = (const float*)d_in[6];
    const float* lb1_w  = (const float*)d_in[7];
    const float* lb1_b  = (const float*)d_in[8];
    const float* lb2_w  = (const float*)d_in[9];
    const float* lb2_b  = (const float*)d_in[10];
    const float* dec_W  = (const float*)d_in[11];
    const float* dec_b  = (const float*)d_in[12];
    const float* proj_w = (const float*)d_in[13];
    const float* proj_b = (const float*)d_in[14];
    float* out = (float*)d_out;

    static int attr_done = 0;
    if (!attr_done) {
        cudaFuncSetAttribute(gemm1_kernel, cudaFuncAttributeMaxDynamicSharedMemorySize, SMEMB);
        cudaFuncSetAttribute(gemm2_kernel, cudaFuncAttributeMaxDynamicSharedMemorySize, SMEMB);
        attr_done = 1;
    }

    zero_kernel<<<(Bz * Nn * KP) / 256, 256>>>();
    splitG_kernel<<<(Kk * Nn * Nn) / 256, 256>>>(G);
    meta1_kernel<<<BT, 128>>>(x_meta, lw1_w, lw1_b, lb1_w, lb1_b);
    meta2_kernel<<<dim3(WMC / 256, BT / 16), 256>>>(lw2_w, lw2_b);
    meta2b_kernel<<<BT, 256>>>(lb2_w, lb2_b);
    wmT_kernel<<<dim3(KP / 32, BT), 256>>>();
    decWT_kernel<<<1, 256>>>(dec_W);

    // encoder
    for (int t = 0; t < Tt; t++) {
        xrow_kernel<<<(Bz * Nn) / 256, 256>>>(x_seq, t);
        gemm1_kernel<<<dim3(NQ / 128, Nn / 128, Kk), 256, SMEMB>>>();
        gemm2_kernel<<<dim3(Nn / 128, Bz, 2), 256, SMEMB>>>(t, 1, nullptr);
    }

    // decoder
    zerox_kernel<<<(Bz * Nn) / 256, 256>>>();
    for (int s = 0; s < HOR; s++) {
        gemm1_kernel<<<dim3(NQ / 128, Nn / 128, Kk), 256, SMEMB>>>();
        gemm2_kernel<<<dim3(Nn / 128, Bz, 2), 256, SMEMB>>>(0, 0, dec_b);
        proj_kernel<<<(Bz * Nn) / 256, 256>>>(proj_w, proj_b, out, s);
    }
}